// round 14
// baseline (speedup 1.0000x reference)
#include <cuda_runtime.h>
#include <cuda_bf16.h>
#include <cstdint>

// ---------------------------------------------------------------------------
// AtomUpdateBlock on GB300 (plain sm_103 feature set).
// Edge stage: CSR sort (packed eid|aid) + R12-proven per-edge 8-stage cp.async
//             pipelined run-accumulated scatter.
// MLP stage: fused 5-layer HMMA kernel + cp.async weight staging (single new
//            change this round, for clean attribution).
// ---------------------------------------------------------------------------

#define CAP_ATOMS 131072
#define CAP_EDGES (1 << 21)

__device__ float              g_x2[CAP_ATOMS * 128];
__device__ int                g_counts[CAP_ATOMS];
__device__ int                g_offs  [CAP_ATOMS];
__device__ int                g_cursor[CAP_ATOMS];
__device__ int                g_bsums [256];
__device__ unsigned long long g_pk    [CAP_EDGES];   // lo32=eid, hi32=aid

__device__ __forceinline__ float ssilu(float x) {
    return x * (1.0f / (1.0f + __expf(-x))) * 1.6666666666666667f;
}

// ============================ zero / CSR build ==============================
__global__ void __launch_bounds__(256) zero_kernel(float* __restrict__ p, int n4) {
    int i = blockIdx.x * blockDim.x + threadIdx.x;
    int stride = gridDim.x * blockDim.x;
    float4 z = make_float4(0.f, 0.f, 0.f, 0.f);
    for (; i < n4; i += stride) ((float4*)p)[i] = z;
}

__global__ void __launch_bounds__(256) zero_int_kernel(int* __restrict__ p, int n4) {
    int i = blockIdx.x * blockDim.x + threadIdx.x;
    int stride = gridDim.x * blockDim.x;
    int4 z = make_int4(0, 0, 0, 0);
    for (; i < n4; i += stride) ((int4*)p)[i] = z;
}

__global__ void __launch_bounds__(256) hist_kernel(const int* __restrict__ idj,
                                                   int* __restrict__ counts, int E) {
    int i = blockIdx.x * blockDim.x + threadIdx.x;
    int stride = gridDim.x * blockDim.x;
    for (; i < E; i += stride) atomicAdd(&counts[__ldg(idj + i)], 1);
}

__global__ void __launch_bounds__(256) scan1_kernel(const int* __restrict__ counts,
                                                    int* __restrict__ offs,
                                                    int* __restrict__ bsums, int nAtoms) {
    __shared__ int sm[256];
    int t = threadIdx.x;
    int base = blockIdx.x * 1024 + t * 4;
    int c0 = 0, c1 = 0, c2 = 0, c3 = 0;
    if (base + 3 < nAtoms) {
        int4 c = *(const int4*)(counts + base);
        c0 = c.x; c1 = c.y; c2 = c.z; c3 = c.w;
    } else {
        if (base + 0 < nAtoms) c0 = counts[base + 0];
        if (base + 1 < nAtoms) c1 = counts[base + 1];
        if (base + 2 < nAtoms) c2 = counts[base + 2];
        if (base + 3 < nAtoms) c3 = counts[base + 3];
    }
    int T = c0 + c1 + c2 + c3;
    sm[t] = T;
    __syncthreads();
    for (int d = 1; d < 256; d <<= 1) {
        int v = (t >= d) ? sm[t - d] : 0;
        __syncthreads();
        sm[t] += v;
        __syncthreads();
    }
    int o = sm[t] - T;
    if (t == 255) bsums[blockIdx.x] = sm[255];
    if (base + 0 < nAtoms) offs[base + 0] = o; o += c0;
    if (base + 1 < nAtoms) offs[base + 1] = o; o += c1;
    if (base + 2 < nAtoms) offs[base + 2] = o; o += c2;
    if (base + 3 < nAtoms) offs[base + 3] = o;
}

__global__ void __launch_bounds__(128) scan2_kernel(int* __restrict__ bsums, int nb) {
    __shared__ int sm[128];
    int t = threadIdx.x;
    int v = (t < nb) ? bsums[t] : 0;
    sm[t] = v;
    __syncthreads();
    for (int d = 1; d < 128; d <<= 1) {
        int x = (t >= d) ? sm[t - d] : 0;
        __syncthreads();
        sm[t] += x;
        __syncthreads();
    }
    bsums[t] = sm[t] - v;
}

__global__ void __launch_bounds__(256) scan3_kernel(const int* __restrict__ bsums,
                                                    int* __restrict__ offs,
                                                    int* __restrict__ cursor,
                                                    int nAtoms) {
    int i = blockIdx.x * blockDim.x + threadIdx.x;
    if (i < nAtoms) {
        int v = offs[i] + __ldg(bsums + (i >> 10));
        offs[i] = v;
        cursor[i] = v;
    }
}

__global__ void __launch_bounds__(256) fill_kernel(const int* __restrict__ idj,
                                                   int* __restrict__ cursor,
                                                   unsigned long long* __restrict__ pk,
                                                   int E) {
    int i = blockIdx.x * blockDim.x + threadIdx.x;
    int stride = gridDim.x * blockDim.x;
    for (; i < E; i += stride) {
        int a = __ldg(idj + i);
        int p = atomicAdd(&cursor[a], 1);
        pk[p] = (unsigned long long)(unsigned)i
              | ((unsigned long long)(unsigned)a << 32);
    }
}

// ============================ pipelined sorted scatter (R12) ================
#define CHUNK   64
#define STAGES  8
#define STG_B   576                        // 512B m row + 64B rbf
#define WARP_SMEM (512 + STAGES * STG_B)   // 512B pk + stages = 5120B

__global__ void __launch_bounds__(256, 2) edge_pipe_kernel(
    const float* __restrict__ m,                 // [E,128]
    const float* __restrict__ rbf,               // [E,16]
    const unsigned long long* __restrict__ pk,   // [E] sorted: eid|aid<<32
    const float* __restrict__ Wr,                // [128,16]
    float*       __restrict__ out,               // [nAtoms,128] zeroed
    int E)
{
    __shared__ __align__(16) char smem[8 * WARP_SMEM];

    const int lane   = threadIdx.x & 31;
    const int wlocal = threadIdx.x >> 5;
    const int warp   = (blockIdx.x * blockDim.x + threadIdx.x) >> 5;
    const int base   = warp * CHUNK;
    if (base >= E) return;
    const int n  = (base + CHUNK <= E) ? CHUNK : (E - base);
    const int c0 = lane * 4;

    char* ws = smem + wlocal * WARP_SMEM;
    unsigned long long* s_pk = (unsigned long long*)ws;
    char* stages = ws + 512;
    uint32_t sbase;
    asm("{ .reg .u64 t; cvta.to.shared.u64 t, %1; cvt.u32.u64 %0, t; }"
        : "=r"(sbase) : "l"(stages));

    // ---- weights packed f32x2 in registers
    unsigned long long wp0[16], wp1[16];
#pragma unroll
    for (int k = 0; k < 16; ++k) {
        float a = __ldg(&Wr[(c0 + 0) * 16 + k]);
        float b = __ldg(&Wr[(c0 + 1) * 16 + k]);
        float c = __ldg(&Wr[(c0 + 2) * 16 + k]);
        float d = __ldg(&Wr[(c0 + 3) * 16 + k]);
        asm("mov.b64 %0, {%1, %2};" : "=l"(wp0[k]) : "f"(a), "f"(b));
        asm("mov.b64 %0, {%1, %2};" : "=l"(wp1[k]) : "f"(c), "f"(d));
    }

    // ---- preload this chunk's pk entries to smem
    for (int j = lane; j < CHUNK; j += 32) {
        int gi = base + j;
        s_pk[j] = (gi < E) ? __ldg(pk + gi) : 0ull;
    }
    __syncwarp();

    // ---- pipeline prologue: issue STAGES edges
#pragma unroll
    for (int s = 0; s < STAGES; ++s) {
        if (s < n) {
            int e = (int)(unsigned)s_pk[s];
            uint32_t dm = sbase + s * STG_B + lane * 16;
            asm volatile("cp.async.ca.shared.global [%0], [%1], 16;"
                         :: "r"(dm), "l"(m + (size_t)e * 128 + lane * 4)
                         : "memory");
            if (lane < 4) {
                uint32_t dr = sbase + s * STG_B + 512 + lane * 16;
                asm volatile("cp.async.ca.shared.global [%0], [%1], 16;"
                             :: "r"(dr), "l"(rbf + (size_t)e * 16 + lane * 4)
                             : "memory");
            }
        }
        asm volatile("cp.async.commit_group;" ::: "memory");
    }

    int cur = (int)(s_pk[0] >> 32);
    float ax = 0.f, ay = 0.f, az = 0.f, aw = 0.f;

    for (int i = 0; i < n; ++i) {
        asm volatile("cp.async.wait_group 7;" ::: "memory");
        __syncwarp();

        const int s = i & (STAGES - 1);
        const int a = (int)(s_pk[i] >> 32);
        if (a != cur) {                          // warp-uniform
            float* dst = out + (size_t)cur * 128 + c0;
            asm volatile("red.global.add.v4.f32 [%0], {%1, %2, %3, %4};"
                         :: "l"(dst), "f"(ax), "f"(ay), "f"(az), "f"(aw)
                         : "memory");
            ax = ay = az = aw = 0.f;
            cur = a;
        }

        const float* st = (const float*)(stages + s * STG_B);
        float4 mv = *(const float4*)(st + lane * 4);
        float4 r0 = *(const float4*)(st + 128);
        float4 r1 = *(const float4*)(st + 132);
        float4 r2 = *(const float4*)(st + 136);
        float4 r3 = *(const float4*)(st + 140);

        float rk[16] = {r0.x, r0.y, r0.z, r0.w, r1.x, r1.y, r1.z, r1.w,
                        r2.x, r2.y, r2.z, r2.w, r3.x, r3.y, r3.z, r3.w};
        unsigned long long d01 = 0ull, d23 = 0ull;
#pragma unroll
        for (int k = 0; k < 16; ++k) {
            unsigned long long rp;
            asm("mov.b64 %0, {%1, %1};" : "=l"(rp) : "f"(rk[k]));
            asm("fma.rn.f32x2 %0, %1, %2, %0;" : "+l"(d01) : "l"(rp), "l"(wp0[k]));
            asm("fma.rn.f32x2 %0, %1, %2, %0;" : "+l"(d23) : "l"(rp), "l"(wp1[k]));
        }
        float v0, v1, v2, v3;
        asm("mov.b64 {%0, %1}, %2;" : "=f"(v0), "=f"(v1) : "l"(d01));
        asm("mov.b64 {%0, %1}, %2;" : "=f"(v2), "=f"(v3) : "l"(d23));
        ax = fmaf(v0, mv.x, ax);
        ay = fmaf(v1, mv.y, ay);
        az = fmaf(v2, mv.z, az);
        aw = fmaf(v3, mv.w, aw);

        // ---- refill slot s with edge i+STAGES
        __syncwarp();
        const int j = i + STAGES;
        if (j < n) {
            int e = (int)(unsigned)s_pk[j];
            uint32_t dm = sbase + s * STG_B + lane * 16;
            asm volatile("cp.async.ca.shared.global [%0], [%1], 16;"
                         :: "r"(dm), "l"(m + (size_t)e * 128 + lane * 4)
                         : "memory");
            if (lane < 4) {
                uint32_t dr = sbase + s * STG_B + 512 + lane * 16;
                asm volatile("cp.async.ca.shared.global [%0], [%1], 16;"
                             :: "r"(dr), "l"(rbf + (size_t)e * 16 + lane * 4)
                             : "memory");
            }
        }
        asm volatile("cp.async.commit_group;" ::: "memory");
    }

    float* dst = out + (size_t)cur * 128 + c0;
    asm volatile("red.global.add.v4.f32 [%0], {%1, %2, %3, %4};"
                 :: "l"(dst), "f"(ax), "f"(ay), "f"(az), "f"(aw) : "memory");
}

// ============================ fused MLP (+ weight staging) ==================
#define SPAD 136
#define TILE (128 * SPAD)
#define WSTG_BYTES 65536
#define MLP_DSMEM (4 * TILE * 2 + WSTG_BYTES)     // 204800 B

__device__ __forceinline__ void split_store(
    __nv_bfloat16* __restrict__ hi, __nv_bfloat16* __restrict__ lo,
    int idx, float x, float y)
{
    __nv_bfloat16 hx = __float2bfloat16_rn(x);
    __nv_bfloat16 hy = __float2bfloat16_rn(y);
    __nv_bfloat162 hp = __halves2bfloat162(hx, hy);
    __nv_bfloat162 lp = __halves2bfloat162(
        __float2bfloat16_rn(x - __bfloat162float(hx)),
        __float2bfloat16_rn(y - __bfloat162float(hy)));
    *(uint32_t*)&hi[idx] = *(uint32_t*)&hp;
    *(uint32_t*)&lo[idx] = *(uint32_t*)&lp;
}

__device__ __forceinline__ void load_w_split(
    const float* __restrict__ W, __nv_bfloat16* __restrict__ WsH,
    __nv_bfloat16* __restrict__ WsL, int tid)
{
    for (int i = tid; i < 128 * 32; i += 512) {
        int row = i >> 5, k4 = i & 31;
        int so = row * SPAD + 4 * k4;
        float4 w = __ldg((const float4*)(W + (size_t)row * 128) + k4);
        split_store(WsH, WsL, so,     w.x, w.y);
        split_store(WsH, WsL, so + 2, w.z, w.w);
    }
}

__global__ void __launch_bounds__(512, 1) fused_mlp_kernel(
    const float* __restrict__ X,
    const float* __restrict__ W1,
    const float* __restrict__ Wres,
    const float* __restrict__ scale_ptr,
    float*       __restrict__ out,
    int nRows)
{
    extern __shared__ __align__(16) __nv_bfloat16 smem[];
    __nv_bfloat16* XsH = smem;
    __nv_bfloat16* XsL = smem + TILE;
    __nv_bfloat16* WsH = smem + 2 * TILE;
    __nv_bfloat16* WsL = smem + 3 * TILE;
    float*         Wstg = (float*)(smem + 4 * TILE);
    uint32_t wstg_s;
    asm("{ .reg .u64 t; cvta.to.shared.u64 t, %1; cvt.u32.u64 %0, t; }"
        : "=r"(wstg_s) : "l"(Wstg));

    const int tid  = threadIdx.x;
    const int row0 = blockIdx.x * 128;

    for (int i = tid; i < 128 * 32; i += 512) {
        int row = i >> 5, k4 = i & 31;
        int so = row * SPAD + 4 * k4;
        float4 v = make_float4(0.f, 0.f, 0.f, 0.f);
        if (row0 + row < nRows)
            v = __ldg((const float4*)(X + (size_t)(row0 + row) * 128) + k4);
        split_store(XsH, XsL, so,     v.x, v.y);
        split_store(XsH, XsL, so + 2, v.z, v.w);
    }
    load_w_split(W1, WsH, WsL, tid);

    const int wid  = tid >> 5;
    const int lane = tid & 31;
    const int g    = lane >> 2;
    const int ti   = lane & 3;
    const int m0   = (wid & 3) * 32;
    const int nb   = (wid >> 2) * 32;

    const float pre0 = scale_ptr ? __ldg(scale_ptr) : 1.0f;
    const float inv_sqrt2 = 0.70710678118654752440f;

    float res[2][4][4];

#pragma unroll 1
    for (int L = 0; L < 5; ++L) {
        __syncthreads();                 // Xs stores + converted Ws visible

        // stage next layer's raw weights (overlaps the mainloop below)
        if (L < 4) {
            const float* Wn = Wres + (size_t)L * 16384;
#pragma unroll
            for (int j = 0; j < 8; ++j) {
                int i = tid + j * 512;   // float4 index, 4096 total
                asm volatile("cp.async.ca.shared.global [%0], [%1], 16;"
                             :: "r"(wstg_s + i * 16), "l"(Wn + i * 4)
                             : "memory");
            }
            asm volatile("cp.async.commit_group;" ::: "memory");
        }

        float d[2][4][4];
#pragma unroll
        for (int mt = 0; mt < 2; ++mt)
#pragma unroll
            for (int nc = 0; nc < 4; ++nc)
#pragma unroll
                for (int j = 0; j < 4; ++j) d[mt][nc][j] = 0.f;

#pragma unroll
        for (int ks = 0; ks < 8; ++ks) {
            const int k0 = ks * 16;
            uint32_t ah[2][4], al[2][4];
#pragma unroll
            for (int mt = 0; mt < 2; ++mt) {
                const int r = m0 + 16 * mt + g;
                ah[mt][0] = *(const uint32_t*)&XsH[(r)     * SPAD + k0 + 2 * ti];
                ah[mt][1] = *(const uint32_t*)&XsH[(r + 8) * SPAD + k0 + 2 * ti];
                ah[mt][2] = *(const uint32_t*)&XsH[(r)     * SPAD + k0 + 2 * ti + 8];
                ah[mt][3] = *(const uint32_t*)&XsH[(r + 8) * SPAD + k0 + 2 * ti + 8];
                al[mt][0] = *(const uint32_t*)&XsL[(r)     * SPAD + k0 + 2 * ti];
                al[mt][1] = *(const uint32_t*)&XsL[(r + 8) * SPAD + k0 + 2 * ti];
                al[mt][2] = *(const uint32_t*)&XsL[(r)     * SPAD + k0 + 2 * ti + 8];
                al[mt][3] = *(const uint32_t*)&XsL[(r + 8) * SPAD + k0 + 2 * ti + 8];
            }
#pragma unroll
            for (int nc = 0; nc < 4; ++nc) {
                const int n = nb + 8 * nc + g;
                uint32_t b0 = *(const uint32_t*)&WsH[n * SPAD + k0 + 2 * ti];
                uint32_t b1 = *(const uint32_t*)&WsH[n * SPAD + k0 + 2 * ti + 8];
#pragma unroll
                for (int mt = 0; mt < 2; ++mt) {
                    asm volatile(
                        "mma.sync.aligned.m16n8k16.row.col.f32.bf16.bf16.f32 "
                        "{%0,%1,%2,%3}, {%4,%5,%6,%7}, {%8,%9}, {%0,%1,%2,%3};"
                        : "+f"(d[mt][nc][0]), "+f"(d[mt][nc][1]),
                          "+f"(d[mt][nc][2]), "+f"(d[mt][nc][3])
                        : "r"(ah[mt][0]), "r"(ah[mt][1]), "r"(ah[mt][2]), "r"(ah[mt][3]),
                          "r"(b0), "r"(b1));
                    asm volatile(
                        "mma.sync.aligned.m16n8k16.row.col.f32.bf16.bf16.f32 "
                        "{%0,%1,%2,%3}, {%4,%5,%6,%7}, {%8,%9}, {%0,%1,%2,%3};"
                        : "+f"(d[mt][nc][0]), "+f"(d[mt][nc][1]),
                          "+f"(d[mt][nc][2]), "+f"(d[mt][nc][3])
                        : "r"(al[mt][0]), "r"(al[mt][1]), "r"(al[mt][2]), "r"(al[mt][3]),
                          "r"(b0), "r"(b1));
                }
            }
#pragma unroll
            for (int nc = 0; nc < 4; ++nc) {
                const int n = nb + 8 * nc + g;
                uint32_t b0 = *(const uint32_t*)&WsL[n * SPAD + k0 + 2 * ti];
                uint32_t b1 = *(const uint32_t*)&WsL[n * SPAD + k0 + 2 * ti + 8];
#pragma unroll
                for (int mt = 0; mt < 2; ++mt) {
                    asm volatile(
                        "mma.sync.aligned.m16n8k16.row.col.f32.bf16.bf16.f32 "
                        "{%0,%1,%2,%3}, {%4,%5,%6,%7}, {%8,%9}, {%0,%1,%2,%3};"
                        : "+f"(d[mt][nc][0]), "+f"(d[mt][nc][1]),
                          "+f"(d[mt][nc][2]), "+f"(d[mt][nc][3])
                        : "r"(ah[mt][0]), "r"(ah[mt][1]), "r"(ah[mt][2]), "r"(ah[mt][3]),
                          "r"(b0), "r"(b1));
                }
            }
        }

        __syncthreads();                 // everyone done reading Xs/Ws

        const float pre   = (L == 0) ? pre0 : 1.0f;
        const bool addres = (L == 2) || (L == 4);
        const bool saver  = (L == 0) || (L == 2);

#pragma unroll
        for (int mt = 0; mt < 2; ++mt) {
#pragma unroll
            for (int nc = 0; nc < 4; ++nc) {
                float v[4];
#pragma unroll
                for (int j = 0; j < 4; ++j) {
                    float y = ssilu(pre * d[mt][nc][j]);
                    if (addres) y = (res[mt][nc][j] + y) * inv_sqrt2;
                    if (saver)  res[mt][nc][j] = y;
                    v[j] = y;
                }
                const int ra = m0 + 16 * mt + g;
                const int rb = ra + 8;
                const int c  = nb + 8 * nc + 2 * ti;
                if (L < 4) {
                    split_store(XsH, XsL, ra * SPAD + c, v[0], v[1]);
                    split_store(XsH, XsL, rb * SPAD + c, v[2], v[3]);
                } else {
                    if (row0 + ra < nRows)
                        *(float2*)&out[(size_t)(row0 + ra) * 128 + c] =
                            make_float2(v[0], v[1]);
                    if (row0 + rb < nRows)
                        *(float2*)&out[(size_t)(row0 + rb) * 128 + c] =
                            make_float2(v[2], v[3]);
                }
            }
        }

        // convert staged weights (smem->smem, no global latency)
        if (L < 4) {
            asm volatile("cp.async.wait_group 0;" ::: "memory");
            for (int i = tid; i < 128 * 32; i += 512) {
                int row = i >> 5, k4 = i & 31;
                float4 w = ((const float4*)Wstg)[i];
                int so = row * SPAD + 4 * k4;
                split_store(WsH, WsL, so,     w.x, w.y);
                split_store(WsH, WsL, so + 2, w.z, w.w);
            }
        }
    }
}

// ---------------------------------------------------------------------------
extern "C" void kernel_launch(void* const* d_in, const int* in_sizes, int n_in,
                              void* d_out, int out_size)
{
    // metadata order: nAtoms, m, rbf, id_j, W_rbf, scale, W1, W_res
    const float* m     = (const float*)d_in[1];
    const float* rbf   = (const float*)d_in[2];
    const int*   idj   = (const int*)  d_in[3];
    const float* Wrbf  = (const float*)d_in[4];
    const float* scale = (const float*)d_in[5];
    const float* W1    = (const float*)d_in[6];
    const float* Wres  = (const float*)d_in[7];

    int E      = in_sizes[1] / 128;
    int nAtoms = out_size / 128;
    if (nAtoms > CAP_ATOMS) nAtoms = CAP_ATOMS;
    if (E > CAP_EDGES) E = CAP_EDGES;

    float* px2 = nullptr;
    int *pcounts = nullptr, *poffs = nullptr, *pcursor = nullptr, *pbsums = nullptr;
    unsigned long long* ppk = nullptr;
    cudaGetSymbolAddress((void**)&px2, g_x2);
    cudaGetSymbolAddress((void**)&pcounts, g_counts);
    cudaGetSymbolAddress((void**)&poffs,   g_offs);
    cudaGetSymbolAddress((void**)&pcursor, g_cursor);
    cudaGetSymbolAddress((void**)&pbsums,  g_bsums);
    cudaGetSymbolAddress((void**)&ppk,     g_pk);

    cudaFuncSetAttribute(fused_mlp_kernel,
                         cudaFuncAttributeMaxDynamicSharedMemorySize, MLP_DSMEM);

    // CSR sort of edges by atom (packed eid|aid)
    zero_int_kernel<<<256, 256>>>(pcounts, CAP_ATOMS / 4);
    hist_kernel<<<2048, 256>>>(idj, pcounts, E);
    int nb = (nAtoms + 1023) / 1024;
    scan1_kernel<<<nb, 256>>>(pcounts, poffs, pbsums, nAtoms);
    scan2_kernel<<<1, 128>>>(pbsums, nb);
    scan3_kernel<<<(nAtoms + 255) / 256, 256>>>(pbsums, poffs, pcursor, nAtoms);
    fill_kernel<<<2048, 256>>>(idj, pcursor, ppk, E);

    // zero accumulator + per-edge pipelined scatter (R12)
    int n4 = nAtoms * 128 / 4;
    zero_kernel<<<2048, 256>>>(px2, n4);
    int nchunks = (E + CHUNK - 1) / CHUNK;
    edge_pipe_kernel<<<(nchunks + 7) / 8, 256>>>(m, rbf, ppk, Wrbf, px2, E);

    // fused MLP
    int grid = (nAtoms + 127) / 128;
    fused_mlp_kernel<<<grid, 512, MLP_DSMEM>>>(px2, W1, Wres, scale,
                                               (float*)d_out, nAtoms);
}

// round 15
// speedup vs baseline: 1.1201x; 1.1201x over previous
#include <cuda_runtime.h>
#include <cuda_fp16.h>
#include <cstdint>

// ---------------------------------------------------------------------------
// AtomUpdateBlock on GB300 (plain sm_103 feature set).
// Edge stage: CSR sort (packed eid|aid) + R12-proven per-edge 8-stage cp.async
//             pipelined run-accumulated scatter (verbatim).
// MLP stage: fused 5-layer HMMA kernel, fp16 2-TERM split:
//            D = Xh*W16 + Xl*W16  (X split exact; only W quantization error,
//            rel ~1.4e-4/layer).  33% fewer MMAs + LDS than bf16 3-term.
// ---------------------------------------------------------------------------

#define CAP_ATOMS 131072
#define CAP_EDGES (1 << 21)

__device__ float              g_x2[CAP_ATOMS * 128];
__device__ int                g_counts[CAP_ATOMS];
__device__ int                g_offs  [CAP_ATOMS];
__device__ int                g_cursor[CAP_ATOMS];
__device__ int                g_bsums [256];
__device__ unsigned long long g_pk    [CAP_EDGES];   // lo32=eid, hi32=aid

__device__ __forceinline__ float ssilu(float x) {
    return x * (1.0f / (1.0f + __expf(-x))) * 1.6666666666666667f;
}

// ============================ zero / CSR build ==============================
__global__ void __launch_bounds__(256) zero_kernel(float* __restrict__ p, int n4) {
    int i = blockIdx.x * blockDim.x + threadIdx.x;
    int stride = gridDim.x * blockDim.x;
    float4 z = make_float4(0.f, 0.f, 0.f, 0.f);
    for (; i < n4; i += stride) ((float4*)p)[i] = z;
}

__global__ void __launch_bounds__(256) zero_int_kernel(int* __restrict__ p, int n4) {
    int i = blockIdx.x * blockDim.x + threadIdx.x;
    int stride = gridDim.x * blockDim.x;
    int4 z = make_int4(0, 0, 0, 0);
    for (; i < n4; i += stride) ((int4*)p)[i] = z;
}

__global__ void __launch_bounds__(256) hist_kernel(const int* __restrict__ idj,
                                                   int* __restrict__ counts, int E) {
    int i = blockIdx.x * blockDim.x + threadIdx.x;
    int stride = gridDim.x * blockDim.x;
    for (; i < E; i += stride) atomicAdd(&counts[__ldg(idj + i)], 1);
}

__global__ void __launch_bounds__(256) scan1_kernel(const int* __restrict__ counts,
                                                    int* __restrict__ offs,
                                                    int* __restrict__ bsums, int nAtoms) {
    __shared__ int sm[256];
    int t = threadIdx.x;
    int base = blockIdx.x * 1024 + t * 4;
    int c0 = 0, c1 = 0, c2 = 0, c3 = 0;
    if (base + 3 < nAtoms) {
        int4 c = *(const int4*)(counts + base);
        c0 = c.x; c1 = c.y; c2 = c.z; c3 = c.w;
    } else {
        if (base + 0 < nAtoms) c0 = counts[base + 0];
        if (base + 1 < nAtoms) c1 = counts[base + 1];
        if (base + 2 < nAtoms) c2 = counts[base + 2];
        if (base + 3 < nAtoms) c3 = counts[base + 3];
    }
    int T = c0 + c1 + c2 + c3;
    sm[t] = T;
    __syncthreads();
    for (int d = 1; d < 256; d <<= 1) {
        int v = (t >= d) ? sm[t - d] : 0;
        __syncthreads();
        sm[t] += v;
        __syncthreads();
    }
    int o = sm[t] - T;
    if (t == 255) bsums[blockIdx.x] = sm[255];
    if (base + 0 < nAtoms) offs[base + 0] = o; o += c0;
    if (base + 1 < nAtoms) offs[base + 1] = o; o += c1;
    if (base + 2 < nAtoms) offs[base + 2] = o; o += c2;
    if (base + 3 < nAtoms) offs[base + 3] = o;
}

__global__ void __launch_bounds__(128) scan2_kernel(int* __restrict__ bsums, int nb) {
    __shared__ int sm[128];
    int t = threadIdx.x;
    int v = (t < nb) ? bsums[t] : 0;
    sm[t] = v;
    __syncthreads();
    for (int d = 1; d < 128; d <<= 1) {
        int x = (t >= d) ? sm[t - d] : 0;
        __syncthreads();
        sm[t] += x;
        __syncthreads();
    }
    bsums[t] = sm[t] - v;
}

__global__ void __launch_bounds__(256) scan3_kernel(const int* __restrict__ bsums,
                                                    int* __restrict__ offs,
                                                    int* __restrict__ cursor,
                                                    int nAtoms) {
    int i = blockIdx.x * blockDim.x + threadIdx.x;
    if (i < nAtoms) {
        int v = offs[i] + __ldg(bsums + (i >> 10));
        offs[i] = v;
        cursor[i] = v;
    }
}

__global__ void __launch_bounds__(256) fill_kernel(const int* __restrict__ idj,
                                                   int* __restrict__ cursor,
                                                   unsigned long long* __restrict__ pk,
                                                   int E) {
    int i = blockIdx.x * blockDim.x + threadIdx.x;
    int stride = gridDim.x * blockDim.x;
    for (; i < E; i += stride) {
        int a = __ldg(idj + i);
        int p = atomicAdd(&cursor[a], 1);
        pk[p] = (unsigned long long)(unsigned)i
              | ((unsigned long long)(unsigned)a << 32);
    }
}

// ============================ pipelined sorted scatter (R12) ================
#define CHUNK   64
#define STAGES  8
#define STG_B   576                        // 512B m row + 64B rbf
#define WARP_SMEM (512 + STAGES * STG_B)   // 512B pk + stages = 5120B

__global__ void __launch_bounds__(256, 2) edge_pipe_kernel(
    const float* __restrict__ m,                 // [E,128]
    const float* __restrict__ rbf,               // [E,16]
    const unsigned long long* __restrict__ pk,   // [E] sorted: eid|aid<<32
    const float* __restrict__ Wr,                // [128,16]
    float*       __restrict__ out,               // [nAtoms,128] zeroed
    int E)
{
    __shared__ __align__(16) char smem[8 * WARP_SMEM];

    const int lane   = threadIdx.x & 31;
    const int wlocal = threadIdx.x >> 5;
    const int warp   = (blockIdx.x * blockDim.x + threadIdx.x) >> 5;
    const int base   = warp * CHUNK;
    if (base >= E) return;
    const int n  = (base + CHUNK <= E) ? CHUNK : (E - base);
    const int c0 = lane * 4;

    char* ws = smem + wlocal * WARP_SMEM;
    unsigned long long* s_pk = (unsigned long long*)ws;
    char* stages = ws + 512;
    uint32_t sbase;
    asm("{ .reg .u64 t; cvta.to.shared.u64 t, %1; cvt.u32.u64 %0, t; }"
        : "=r"(sbase) : "l"(stages));

    // ---- weights packed f32x2 in registers
    unsigned long long wp0[16], wp1[16];
#pragma unroll
    for (int k = 0; k < 16; ++k) {
        float a = __ldg(&Wr[(c0 + 0) * 16 + k]);
        float b = __ldg(&Wr[(c0 + 1) * 16 + k]);
        float c = __ldg(&Wr[(c0 + 2) * 16 + k]);
        float d = __ldg(&Wr[(c0 + 3) * 16 + k]);
        asm("mov.b64 %0, {%1, %2};" : "=l"(wp0[k]) : "f"(a), "f"(b));
        asm("mov.b64 %0, {%1, %2};" : "=l"(wp1[k]) : "f"(c), "f"(d));
    }

    // ---- preload this chunk's pk entries to smem
    for (int j = lane; j < CHUNK; j += 32) {
        int gi = base + j;
        s_pk[j] = (gi < E) ? __ldg(pk + gi) : 0ull;
    }
    __syncwarp();

    // ---- pipeline prologue: issue STAGES edges
#pragma unroll
    for (int s = 0; s < STAGES; ++s) {
        if (s < n) {
            int e = (int)(unsigned)s_pk[s];
            uint32_t dm = sbase + s * STG_B + lane * 16;
            asm volatile("cp.async.ca.shared.global [%0], [%1], 16;"
                         :: "r"(dm), "l"(m + (size_t)e * 128 + lane * 4)
                         : "memory");
            if (lane < 4) {
                uint32_t dr = sbase + s * STG_B + 512 + lane * 16;
                asm volatile("cp.async.ca.shared.global [%0], [%1], 16;"
                             :: "r"(dr), "l"(rbf + (size_t)e * 16 + lane * 4)
                             : "memory");
            }
        }
        asm volatile("cp.async.commit_group;" ::: "memory");
    }

    int cur = (int)(s_pk[0] >> 32);
    float ax = 0.f, ay = 0.f, az = 0.f, aw = 0.f;

    for (int i = 0; i < n; ++i) {
        asm volatile("cp.async.wait_group 7;" ::: "memory");
        __syncwarp();

        const int s = i & (STAGES - 1);
        const int a = (int)(s_pk[i] >> 32);
        if (a != cur) {                          // warp-uniform
            float* dst = out + (size_t)cur * 128 + c0;
            asm volatile("red.global.add.v4.f32 [%0], {%1, %2, %3, %4};"
                         :: "l"(dst), "f"(ax), "f"(ay), "f"(az), "f"(aw)
                         : "memory");
            ax = ay = az = aw = 0.f;
            cur = a;
        }

        const float* st = (const float*)(stages + s * STG_B);
        float4 mv = *(const float4*)(st + lane * 4);
        float4 r0 = *(const float4*)(st + 128);
        float4 r1 = *(const float4*)(st + 132);
        float4 r2 = *(const float4*)(st + 136);
        float4 r3 = *(const float4*)(st + 140);

        float rk[16] = {r0.x, r0.y, r0.z, r0.w, r1.x, r1.y, r1.z, r1.w,
                        r2.x, r2.y, r2.z, r2.w, r3.x, r3.y, r3.z, r3.w};
        unsigned long long d01 = 0ull, d23 = 0ull;
#pragma unroll
        for (int k = 0; k < 16; ++k) {
            unsigned long long rp;
            asm("mov.b64 %0, {%1, %1};" : "=l"(rp) : "f"(rk[k]));
            asm("fma.rn.f32x2 %0, %1, %2, %0;" : "+l"(d01) : "l"(rp), "l"(wp0[k]));
            asm("fma.rn.f32x2 %0, %1, %2, %0;" : "+l"(d23) : "l"(rp), "l"(wp1[k]));
        }
        float v0, v1, v2, v3;
        asm("mov.b64 {%0, %1}, %2;" : "=f"(v0), "=f"(v1) : "l"(d01));
        asm("mov.b64 {%0, %1}, %2;" : "=f"(v2), "=f"(v3) : "l"(d23));
        ax = fmaf(v0, mv.x, ax);
        ay = fmaf(v1, mv.y, ay);
        az = fmaf(v2, mv.z, az);
        aw = fmaf(v3, mv.w, aw);

        // ---- refill slot s with edge i+STAGES
        __syncwarp();
        const int j = i + STAGES;
        if (j < n) {
            int e = (int)(unsigned)s_pk[j];
            uint32_t dm = sbase + s * STG_B + lane * 16;
            asm volatile("cp.async.ca.shared.global [%0], [%1], 16;"
                         :: "r"(dm), "l"(m + (size_t)e * 128 + lane * 4)
                         : "memory");
            if (lane < 4) {
                uint32_t dr = sbase + s * STG_B + 512 + lane * 16;
                asm volatile("cp.async.ca.shared.global [%0], [%1], 16;"
                             :: "r"(dr), "l"(rbf + (size_t)e * 16 + lane * 4)
                             : "memory");
            }
        }
        asm volatile("cp.async.commit_group;" ::: "memory");
    }

    float* dst = out + (size_t)cur * 128 + c0;
    asm volatile("red.global.add.v4.f32 [%0], {%1, %2, %3, %4};"
                 :: "l"(dst), "f"(ax), "f"(ay), "f"(az), "f"(aw) : "memory");
}

// ============================ fused MLP (fp16 2-term) =======================
// out[r,c] = post( sum_k X[r,k] * W[c,k] ), 128x128 tile per CTA.
// X = Xh + Xl (fp16 pair, exact to ~2^-22); W quantized once to fp16.
// D = Xh*W + Xl*W in fp32 accum -> only W-quantization error (~1.4e-4/layer).
#define SPAD 136
#define TILE (128 * SPAD)
#define MLP_DSMEM (3 * TILE * 2)           // XsH, XsL, Ws = 104448 B

__device__ __forceinline__ void split_store_h(
    __half* __restrict__ hi, __half* __restrict__ lo,
    int idx, float x, float y)
{
    __half hx = __float2half_rn(x);
    __half hy = __float2half_rn(y);
    __half lx = __float2half_rn(x - __half2float(hx));
    __half ly = __float2half_rn(y - __half2float(hy));
    __half2 hp = __halves2half2(hx, hy);
    __half2 lp = __halves2half2(lx, ly);
    *(uint32_t*)&hi[idx] = *(uint32_t*)&hp;
    *(uint32_t*)&lo[idx] = *(uint32_t*)&lp;
}

__device__ __forceinline__ void load_w_h(
    const float* __restrict__ W, __half* __restrict__ Ws, int tid)
{
    for (int i = tid; i < 128 * 32; i += 512) {
        int row = i >> 5, k4 = i & 31;
        int so = row * SPAD + 4 * k4;
        float4 w = __ldg((const float4*)(W + (size_t)row * 128) + k4);
        __half2 p0 = __halves2half2(__float2half_rn(w.x), __float2half_rn(w.y));
        __half2 p1 = __halves2half2(__float2half_rn(w.z), __float2half_rn(w.w));
        *(uint2*)&Ws[so] = make_uint2(*(uint32_t*)&p0, *(uint32_t*)&p1);
    }
}

__global__ void __launch_bounds__(512, 1) fused_mlp_kernel(
    const float* __restrict__ X,
    const float* __restrict__ W1,
    const float* __restrict__ Wres,
    const float* __restrict__ scale_ptr,
    float*       __restrict__ out,
    int nRows)
{
    extern __shared__ __align__(16) __half smem[];
    __half* XsH = smem;
    __half* XsL = smem + TILE;
    __half* Ws  = smem + 2 * TILE;

    const int tid  = threadIdx.x;
    const int row0 = blockIdx.x * 128;

    for (int i = tid; i < 128 * 32; i += 512) {
        int row = i >> 5, k4 = i & 31;
        int so = row * SPAD + 4 * k4;
        float4 v = make_float4(0.f, 0.f, 0.f, 0.f);
        if (row0 + row < nRows)
            v = __ldg((const float4*)(X + (size_t)(row0 + row) * 128) + k4);
        split_store_h(XsH, XsL, so,     v.x, v.y);
        split_store_h(XsH, XsL, so + 2, v.z, v.w);
    }
    load_w_h(W1, Ws, tid);

    const int wid  = tid >> 5;
    const int lane = tid & 31;
    const int g    = lane >> 2;
    const int ti   = lane & 3;
    const int m0   = (wid & 3) * 32;
    const int nb   = (wid >> 2) * 32;

    const float pre0 = scale_ptr ? __ldg(scale_ptr) : 1.0f;
    const float inv_sqrt2 = 0.70710678118654752440f;

    float res[2][4][4];

#pragma unroll 1
    for (int L = 0; L < 5; ++L) {
        __syncthreads();                 // Xs/Ws stores visible

        float d[2][4][4];
#pragma unroll
        for (int mt = 0; mt < 2; ++mt)
#pragma unroll
            for (int nc = 0; nc < 4; ++nc)
#pragma unroll
                for (int j = 0; j < 4; ++j) d[mt][nc][j] = 0.f;

#pragma unroll
        for (int ks = 0; ks < 8; ++ks) {
            const int k0 = ks * 16;
            uint32_t ah[2][4], al[2][4];
#pragma unroll
            for (int mt = 0; mt < 2; ++mt) {
                const int r = m0 + 16 * mt + g;
                ah[mt][0] = *(const uint32_t*)&XsH[(r)     * SPAD + k0 + 2 * ti];
                ah[mt][1] = *(const uint32_t*)&XsH[(r + 8) * SPAD + k0 + 2 * ti];
                ah[mt][2] = *(const uint32_t*)&XsH[(r)     * SPAD + k0 + 2 * ti + 8];
                ah[mt][3] = *(const uint32_t*)&XsH[(r + 8) * SPAD + k0 + 2 * ti + 8];
                al[mt][0] = *(const uint32_t*)&XsL[(r)     * SPAD + k0 + 2 * ti];
                al[mt][1] = *(const uint32_t*)&XsL[(r + 8) * SPAD + k0 + 2 * ti];
                al[mt][2] = *(const uint32_t*)&XsL[(r)     * SPAD + k0 + 2 * ti + 8];
                al[mt][3] = *(const uint32_t*)&XsL[(r + 8) * SPAD + k0 + 2 * ti + 8];
            }
#pragma unroll
            for (int nc = 0; nc < 4; ++nc) {
                const int n = nb + 8 * nc + g;
                uint32_t b0 = *(const uint32_t*)&Ws[n * SPAD + k0 + 2 * ti];
                uint32_t b1 = *(const uint32_t*)&Ws[n * SPAD + k0 + 2 * ti + 8];
#pragma unroll
                for (int mt = 0; mt < 2; ++mt) {
                    asm volatile(
                        "mma.sync.aligned.m16n8k16.row.col.f32.f16.f16.f32 "
                        "{%0,%1,%2,%3}, {%4,%5,%6,%7}, {%8,%9}, {%0,%1,%2,%3};"
                        : "+f"(d[mt][nc][0]), "+f"(d[mt][nc][1]),
                          "+f"(d[mt][nc][2]), "+f"(d[mt][nc][3])
                        : "r"(ah[mt][0]), "r"(ah[mt][1]), "r"(ah[mt][2]), "r"(ah[mt][3]),
                          "r"(b0), "r"(b1));
                    asm volatile(
                        "mma.sync.aligned.m16n8k16.row.col.f32.f16.f16.f32 "
                        "{%0,%1,%2,%3}, {%4,%5,%6,%7}, {%8,%9}, {%0,%1,%2,%3};"
                        : "+f"(d[mt][nc][0]), "+f"(d[mt][nc][1]),
                          "+f"(d[mt][nc][2]), "+f"(d[mt][nc][3])
                        : "r"(al[mt][0]), "r"(al[mt][1]), "r"(al[mt][2]), "r"(al[mt][3]),
                          "r"(b0), "r"(b1));
                }
            }
        }

        __syncthreads();                 // everyone done reading Xs/Ws

        const float pre   = (L == 0) ? pre0 : 1.0f;
        const bool addres = (L == 2) || (L == 4);
        const bool saver  = (L == 0) || (L == 2);

#pragma unroll
        for (int mt = 0; mt < 2; ++mt) {
#pragma unroll
            for (int nc = 0; nc < 4; ++nc) {
                float v[4];
#pragma unroll
                for (int j = 0; j < 4; ++j) {
                    float y = ssilu(pre * d[mt][nc][j]);
                    if (addres) y = (res[mt][nc][j] + y) * inv_sqrt2;
                    if (saver)  res[mt][nc][j] = y;
                    v[j] = y;
                }
                const int ra = m0 + 16 * mt + g;
                const int rb = ra + 8;
                const int c  = nb + 8 * nc + 2 * ti;
                if (L < 4) {
                    split_store_h(XsH, XsL, ra * SPAD + c, v[0], v[1]);
                    split_store_h(XsH, XsL, rb * SPAD + c, v[2], v[3]);
                } else {
                    if (row0 + ra < nRows)
                        *(float2*)&out[(size_t)(row0 + ra) * 128 + c] =
                            make_float2(v[0], v[1]);
                    if (row0 + rb < nRows)
                        *(float2*)&out[(size_t)(row0 + rb) * 128 + c] =
                            make_float2(v[2], v[3]);
                }
            }
        }

        if (L < 4) load_w_h(Wres + (size_t)L * 16384, Ws, tid);
    }
}

// ---------------------------------------------------------------------------
extern "C" void kernel_launch(void* const* d_in, const int* in_sizes, int n_in,
                              void* d_out, int out_size)
{
    // metadata order: nAtoms, m, rbf, id_j, W_rbf, scale, W1, W_res
    const float* m     = (const float*)d_in[1];
    const float* rbf   = (const float*)d_in[2];
    const int*   idj   = (const int*)  d_in[3];
    const float* Wrbf  = (const float*)d_in[4];
    const float* scale = (const float*)d_in[5];
    const float* W1    = (const float*)d_in[6];
    const float* Wres  = (const float*)d_in[7];

    int E      = in_sizes[1] / 128;
    int nAtoms = out_size / 128;
    if (nAtoms > CAP_ATOMS) nAtoms = CAP_ATOMS;
    if (E > CAP_EDGES) E = CAP_EDGES;

    float* px2 = nullptr;
    int *pcounts = nullptr, *poffs = nullptr, *pcursor = nullptr, *pbsums = nullptr;
    unsigned long long* ppk = nullptr;
    cudaGetSymbolAddress((void**)&px2, g_x2);
    cudaGetSymbolAddress((void**)&pcounts, g_counts);
    cudaGetSymbolAddress((void**)&poffs,   g_offs);
    cudaGetSymbolAddress((void**)&pcursor, g_cursor);
    cudaGetSymbolAddress((void**)&pbsums,  g_bsums);
    cudaGetSymbolAddress((void**)&ppk,     g_pk);

    cudaFuncSetAttribute(fused_mlp_kernel,
                         cudaFuncAttributeMaxDynamicSharedMemorySize, MLP_DSMEM);

    // CSR sort of edges by atom (packed eid|aid)
    zero_int_kernel<<<256, 256>>>(pcounts, CAP_ATOMS / 4);
    hist_kernel<<<2048, 256>>>(idj, pcounts, E);
    int nb = (nAtoms + 1023) / 1024;
    scan1_kernel<<<nb, 256>>>(pcounts, poffs, pbsums, nAtoms);
    scan2_kernel<<<1, 128>>>(pbsums, nb);
    scan3_kernel<<<(nAtoms + 255) / 256, 256>>>(pbsums, poffs, pcursor, nAtoms);
    fill_kernel<<<2048, 256>>>(idj, pcursor, ppk, E);

    // zero accumulator + per-edge pipelined scatter (R12)
    int n4 = nAtoms * 128 / 4;
    zero_kernel<<<2048, 256>>>(px2, n4);
    int nchunks = (E + CHUNK - 1) / CHUNK;
    edge_pipe_kernel<<<(nchunks + 7) / 8, 256>>>(m, rbf, ppk, Wrbf, px2, E);

    // fused MLP (fp16 2-term)
    int grid = (nAtoms + 127) / 128;
    fused_mlp_kernel<<<grid, 512, MLP_DSMEM>>>(px2, W1, Wres, scale,
                                               (float*)d_out, nAtoms);
}

// round 16
// speedup vs baseline: 1.2137x; 1.0836x over previous
#include <cuda_runtime.h>
#include <cuda_fp16.h>
#include <cstdint>

// ---------------------------------------------------------------------------
// AtomUpdateBlock on GB300 (plain sm_103 feature set).
// Edge stage: CSR sort (packed eid|aid) + per-edge 8-stage cp.async pipelined
//             run-accumulated scatter. CHUNK=128 (R16: amortize per-warp
//             fixed costs 2x vs R12's 64).
// MLP stage: fused 5-layer HMMA kernel, fp16 2-term split (R15-proven).
// ---------------------------------------------------------------------------

#define CAP_ATOMS 131072
#define CAP_EDGES (1 << 21)

__device__ float              g_x2[CAP_ATOMS * 128];
__device__ int                g_counts[CAP_ATOMS];
__device__ int                g_offs  [CAP_ATOMS];
__device__ int                g_cursor[CAP_ATOMS];
__device__ int                g_bsums [256];
__device__ unsigned long long g_pk    [CAP_EDGES];   // lo32=eid, hi32=aid

__device__ __forceinline__ float ssilu(float x) {
    return x * (1.0f / (1.0f + __expf(-x))) * 1.6666666666666667f;
}

// ============================ zero / CSR build ==============================
__global__ void __launch_bounds__(256) zero_kernel(float* __restrict__ p, int n4) {
    int i = blockIdx.x * blockDim.x + threadIdx.x;
    int stride = gridDim.x * blockDim.x;
    float4 z = make_float4(0.f, 0.f, 0.f, 0.f);
    for (; i < n4; i += stride) ((float4*)p)[i] = z;
}

__global__ void __launch_bounds__(256) zero_int_kernel(int* __restrict__ p, int n4) {
    int i = blockIdx.x * blockDim.x + threadIdx.x;
    int stride = gridDim.x * blockDim.x;
    int4 z = make_int4(0, 0, 0, 0);
    for (; i < n4; i += stride) ((int4*)p)[i] = z;
}

__global__ void __launch_bounds__(256) hist_kernel(const int* __restrict__ idj,
                                                   int* __restrict__ counts, int E) {
    int i = blockIdx.x * blockDim.x + threadIdx.x;
    int stride = gridDim.x * blockDim.x;
    for (; i < E; i += stride) atomicAdd(&counts[__ldg(idj + i)], 1);
}

__global__ void __launch_bounds__(256) scan1_kernel(const int* __restrict__ counts,
                                                    int* __restrict__ offs,
                                                    int* __restrict__ bsums, int nAtoms) {
    __shared__ int sm[256];
    int t = threadIdx.x;
    int base = blockIdx.x * 1024 + t * 4;
    int c0 = 0, c1 = 0, c2 = 0, c3 = 0;
    if (base + 3 < nAtoms) {
        int4 c = *(const int4*)(counts + base);
        c0 = c.x; c1 = c.y; c2 = c.z; c3 = c.w;
    } else {
        if (base + 0 < nAtoms) c0 = counts[base + 0];
        if (base + 1 < nAtoms) c1 = counts[base + 1];
        if (base + 2 < nAtoms) c2 = counts[base + 2];
        if (base + 3 < nAtoms) c3 = counts[base + 3];
    }
    int T = c0 + c1 + c2 + c3;
    sm[t] = T;
    __syncthreads();
    for (int d = 1; d < 256; d <<= 1) {
        int v = (t >= d) ? sm[t - d] : 0;
        __syncthreads();
        sm[t] += v;
        __syncthreads();
    }
    int o = sm[t] - T;
    if (t == 255) bsums[blockIdx.x] = sm[255];
    if (base + 0 < nAtoms) offs[base + 0] = o; o += c0;
    if (base + 1 < nAtoms) offs[base + 1] = o; o += c1;
    if (base + 2 < nAtoms) offs[base + 2] = o; o += c2;
    if (base + 3 < nAtoms) offs[base + 3] = o;
}

__global__ void __launch_bounds__(128) scan2_kernel(int* __restrict__ bsums, int nb) {
    __shared__ int sm[128];
    int t = threadIdx.x;
    int v = (t < nb) ? bsums[t] : 0;
    sm[t] = v;
    __syncthreads();
    for (int d = 1; d < 128; d <<= 1) {
        int x = (t >= d) ? sm[t - d] : 0;
        __syncthreads();
        sm[t] += x;
        __syncthreads();
    }
    bsums[t] = sm[t] - v;
}

__global__ void __launch_bounds__(256) scan3_kernel(const int* __restrict__ bsums,
                                                    int* __restrict__ offs,
                                                    int* __restrict__ cursor,
                                                    int nAtoms) {
    int i = blockIdx.x * blockDim.x + threadIdx.x;
    if (i < nAtoms) {
        int v = offs[i] + __ldg(bsums + (i >> 10));
        offs[i] = v;
        cursor[i] = v;
    }
}

__global__ void __launch_bounds__(256) fill_kernel(const int* __restrict__ idj,
                                                   int* __restrict__ cursor,
                                                   unsigned long long* __restrict__ pk,
                                                   int E) {
    int i = blockIdx.x * blockDim.x + threadIdx.x;
    int stride = gridDim.x * blockDim.x;
    for (; i < E; i += stride) {
        int a = __ldg(idj + i);
        int p = atomicAdd(&cursor[a], 1);
        pk[p] = (unsigned long long)(unsigned)i
              | ((unsigned long long)(unsigned)a << 32);
    }
}

// ============================ pipelined sorted scatter ======================
#define CHUNK   128
#define STAGES  8
#define STG_B   576                                // 512B m row + 64B rbf
#define PK_B    (CHUNK * 8)                        // 1024B
#define WARP_SMEM (PK_B + STAGES * STG_B)          // 5632B
// 8 warps/CTA * 5632 = 45056B; 2 CTAs = 90KB < 228KB -> occupancy unchanged.

__global__ void __launch_bounds__(256, 2) edge_pipe_kernel(
    const float* __restrict__ m,                 // [E,128]
    const float* __restrict__ rbf,               // [E,16]
    const unsigned long long* __restrict__ pk,   // [E] sorted: eid|aid<<32
    const float* __restrict__ Wr,                // [128,16]
    float*       __restrict__ out,               // [nAtoms,128] zeroed
    int E)
{
    __shared__ __align__(16) char smem[8 * WARP_SMEM];

    const int lane   = threadIdx.x & 31;
    const int wlocal = threadIdx.x >> 5;
    const int warp   = (blockIdx.x * blockDim.x + threadIdx.x) >> 5;
    const int base   = warp * CHUNK;
    if (base >= E) return;
    const int n  = (base + CHUNK <= E) ? CHUNK : (E - base);
    const int c0 = lane * 4;

    char* ws = smem + wlocal * WARP_SMEM;
    unsigned long long* s_pk = (unsigned long long*)ws;
    char* stages = ws + PK_B;
    uint32_t sbase;
    asm("{ .reg .u64 t; cvta.to.shared.u64 t, %1; cvt.u32.u64 %0, t; }"
        : "=r"(sbase) : "l"(stages));

    // ---- weights packed f32x2 in registers
    unsigned long long wp0[16], wp1[16];
#pragma unroll
    for (int k = 0; k < 16; ++k) {
        float a = __ldg(&Wr[(c0 + 0) * 16 + k]);
        float b = __ldg(&Wr[(c0 + 1) * 16 + k]);
        float c = __ldg(&Wr[(c0 + 2) * 16 + k]);
        float d = __ldg(&Wr[(c0 + 3) * 16 + k]);
        asm("mov.b64 %0, {%1, %2};" : "=l"(wp0[k]) : "f"(a), "f"(b));
        asm("mov.b64 %0, {%1, %2};" : "=l"(wp1[k]) : "f"(c), "f"(d));
    }

    // ---- preload this chunk's pk entries to smem
    for (int j = lane; j < CHUNK; j += 32) {
        int gi = base + j;
        s_pk[j] = (gi < E) ? __ldg(pk + gi) : 0ull;
    }
    __syncwarp();

    // ---- pipeline prologue: issue STAGES edges
#pragma unroll
    for (int s = 0; s < STAGES; ++s) {
        if (s < n) {
            int e = (int)(unsigned)s_pk[s];
            uint32_t dm = sbase + s * STG_B + lane * 16;
            asm volatile("cp.async.ca.shared.global [%0], [%1], 16;"
                         :: "r"(dm), "l"(m + (size_t)e * 128 + lane * 4)
                         : "memory");
            if (lane < 4) {
                uint32_t dr = sbase + s * STG_B + 512 + lane * 16;
                asm volatile("cp.async.ca.shared.global [%0], [%1], 16;"
                             :: "r"(dr), "l"(rbf + (size_t)e * 16 + lane * 4)
                             : "memory");
            }
        }
        asm volatile("cp.async.commit_group;" ::: "memory");
    }

    int cur = (int)(s_pk[0] >> 32);
    float ax = 0.f, ay = 0.f, az = 0.f, aw = 0.f;

    for (int i = 0; i < n; ++i) {
        asm volatile("cp.async.wait_group 7;" ::: "memory");
        __syncwarp();

        const int s = i & (STAGES - 1);
        const int a = (int)(s_pk[i] >> 32);
        if (a != cur) {                          // warp-uniform
            float* dst = out + (size_t)cur * 128 + c0;
            asm volatile("red.global.add.v4.f32 [%0], {%1, %2, %3, %4};"
                         :: "l"(dst), "f"(ax), "f"(ay), "f"(az), "f"(aw)
                         : "memory");
            ax = ay = az = aw = 0.f;
            cur = a;
        }

        const float* st = (const float*)(stages + s * STG_B);
        float4 mv = *(const float4*)(st + lane * 4);
        float4 r0 = *(const float4*)(st + 128);
        float4 r1 = *(const float4*)(st + 132);
        float4 r2 = *(const float4*)(st + 136);
        float4 r3 = *(const float4*)(st + 140);

        float rk[16] = {r0.x, r0.y, r0.z, r0.w, r1.x, r1.y, r1.z, r1.w,
                        r2.x, r2.y, r2.z, r2.w, r3.x, r3.y, r3.z, r3.w};
        unsigned long long d01 = 0ull, d23 = 0ull;
#pragma unroll
        for (int k = 0; k < 16; ++k) {
            unsigned long long rp;
            asm("mov.b64 %0, {%1, %1};" : "=l"(rp) : "f"(rk[k]));
            asm("fma.rn.f32x2 %0, %1, %2, %0;" : "+l"(d01) : "l"(rp), "l"(wp0[k]));
            asm("fma.rn.f32x2 %0, %1, %2, %0;" : "+l"(d23) : "l"(rp), "l"(wp1[k]));
        }
        float v0, v1, v2, v3;
        asm("mov.b64 {%0, %1}, %2;" : "=f"(v0), "=f"(v1) : "l"(d01));
        asm("mov.b64 {%0, %1}, %2;" : "=f"(v2), "=f"(v3) : "l"(d23));
        ax = fmaf(v0, mv.x, ax);
        ay = fmaf(v1, mv.y, ay);
        az = fmaf(v2, mv.z, az);
        aw = fmaf(v3, mv.w, aw);

        // ---- refill slot s with edge i+STAGES
        __syncwarp();
        const int j = i + STAGES;
        if (j < n) {
            int e = (int)(unsigned)s_pk[j];
            uint32_t dm = sbase + s * STG_B + lane * 16;
            asm volatile("cp.async.ca.shared.global [%0], [%1], 16;"
                         :: "r"(dm), "l"(m + (size_t)e * 128 + lane * 4)
                         : "memory");
            if (lane < 4) {
                uint32_t dr = sbase + s * STG_B + 512 + lane * 16;
                asm volatile("cp.async.ca.shared.global [%0], [%1], 16;"
                             :: "r"(dr), "l"(rbf + (size_t)e * 16 + lane * 4)
                             : "memory");
            }
        }
        asm volatile("cp.async.commit_group;" ::: "memory");
    }

    float* dst = out + (size_t)cur * 128 + c0;
    asm volatile("red.global.add.v4.f32 [%0], {%1, %2, %3, %4};"
                 :: "l"(dst), "f"(ax), "f"(ay), "f"(az), "f"(aw) : "memory");
}

// ============================ fused MLP (fp16 2-term, R15) ==================
#define SPAD 136
#define TILE (128 * SPAD)
#define MLP_DSMEM (3 * TILE * 2)           // XsH, XsL, Ws = 104448 B

__device__ __forceinline__ void split_store_h(
    __half* __restrict__ hi, __half* __restrict__ lo,
    int idx, float x, float y)
{
    __half hx = __float2half_rn(x);
    __half hy = __float2half_rn(y);
    __half lx = __float2half_rn(x - __half2float(hx));
    __half ly = __float2half_rn(y - __half2float(hy));
    __half2 hp = __halves2half2(hx, hy);
    __half2 lp = __halves2half2(lx, ly);
    *(uint32_t*)&hi[idx] = *(uint32_t*)&hp;
    *(uint32_t*)&lo[idx] = *(uint32_t*)&lp;
}

__device__ __forceinline__ void load_w_h(
    const float* __restrict__ W, __half* __restrict__ Ws, int tid)
{
    for (int i = tid; i < 128 * 32; i += 512) {
        int row = i >> 5, k4 = i & 31;
        int so = row * SPAD + 4 * k4;
        float4 w = __ldg((const float4*)(W + (size_t)row * 128) + k4);
        __half2 p0 = __halves2half2(__float2half_rn(w.x), __float2half_rn(w.y));
        __half2 p1 = __halves2half2(__float2half_rn(w.z), __float2half_rn(w.w));
        *(uint2*)&Ws[so] = make_uint2(*(uint32_t*)&p0, *(uint32_t*)&p1);
    }
}

__global__ void __launch_bounds__(512, 1) fused_mlp_kernel(
    const float* __restrict__ X,
    const float* __restrict__ W1,
    const float* __restrict__ Wres,
    const float* __restrict__ scale_ptr,
    float*       __restrict__ out,
    int nRows)
{
    extern __shared__ __align__(16) __half smem[];
    __half* XsH = smem;
    __half* XsL = smem + TILE;
    __half* Ws  = smem + 2 * TILE;

    const int tid  = threadIdx.x;
    const int row0 = blockIdx.x * 128;

    for (int i = tid; i < 128 * 32; i += 512) {
        int row = i >> 5, k4 = i & 31;
        int so = row * SPAD + 4 * k4;
        float4 v = make_float4(0.f, 0.f, 0.f, 0.f);
        if (row0 + row < nRows)
            v = __ldg((const float4*)(X + (size_t)(row0 + row) * 128) + k4);
        split_store_h(XsH, XsL, so,     v.x, v.y);
        split_store_h(XsH, XsL, so + 2, v.z, v.w);
    }
    load_w_h(W1, Ws, tid);

    const int wid  = tid >> 5;
    const int lane = tid & 31;
    const int g    = lane >> 2;
    const int ti   = lane & 3;
    const int m0   = (wid & 3) * 32;
    const int nb   = (wid >> 2) * 32;

    const float pre0 = scale_ptr ? __ldg(scale_ptr) : 1.0f;
    const float inv_sqrt2 = 0.70710678118654752440f;

    float res[2][4][4];

#pragma unroll 1
    for (int L = 0; L < 5; ++L) {
        __syncthreads();                 // Xs/Ws stores visible

        float d[2][4][4];
#pragma unroll
        for (int mt = 0; mt < 2; ++mt)
#pragma unroll
            for (int nc = 0; nc < 4; ++nc)
#pragma unroll
                for (int j = 0; j < 4; ++j) d[mt][nc][j] = 0.f;

#pragma unroll
        for (int ks = 0; ks < 8; ++ks) {
            const int k0 = ks * 16;
            uint32_t ah[2][4], al[2][4];
#pragma unroll
            for (int mt = 0; mt < 2; ++mt) {
                const int r = m0 + 16 * mt + g;
                ah[mt][0] = *(const uint32_t*)&XsH[(r)     * SPAD + k0 + 2 * ti];
                ah[mt][1] = *(const uint32_t*)&XsH[(r + 8) * SPAD + k0 + 2 * ti];
                ah[mt][2] = *(const uint32_t*)&XsH[(r)     * SPAD + k0 + 2 * ti + 8];
                ah[mt][3] = *(const uint32_t*)&XsH[(r + 8) * SPAD + k0 + 2 * ti + 8];
                al[mt][0] = *(const uint32_t*)&XsL[(r)     * SPAD + k0 + 2 * ti];
                al[mt][1] = *(const uint32_t*)&XsL[(r + 8) * SPAD + k0 + 2 * ti];
                al[mt][2] = *(const uint32_t*)&XsL[(r)     * SPAD + k0 + 2 * ti + 8];
                al[mt][3] = *(const uint32_t*)&XsL[(r + 8) * SPAD + k0 + 2 * ti + 8];
            }
#pragma unroll
            for (int nc = 0; nc < 4; ++nc) {
                const int n = nb + 8 * nc + g;
                uint32_t b0 = *(const uint32_t*)&Ws[n * SPAD + k0 + 2 * ti];
                uint32_t b1 = *(const uint32_t*)&Ws[n * SPAD + k0 + 2 * ti + 8];
#pragma unroll
                for (int mt = 0; mt < 2; ++mt) {
                    asm volatile(
                        "mma.sync.aligned.m16n8k16.row.col.f32.f16.f16.f32 "
                        "{%0,%1,%2,%3}, {%4,%5,%6,%7}, {%8,%9}, {%0,%1,%2,%3};"
                        : "+f"(d[mt][nc][0]), "+f"(d[mt][nc][1]),
                          "+f"(d[mt][nc][2]), "+f"(d[mt][nc][3])
                        : "r"(ah[mt][0]), "r"(ah[mt][1]), "r"(ah[mt][2]), "r"(ah[mt][3]),
                          "r"(b0), "r"(b1));
                    asm volatile(
                        "mma.sync.aligned.m16n8k16.row.col.f32.f16.f16.f32 "
                        "{%0,%1,%2,%3}, {%4,%5,%6,%7}, {%8,%9}, {%0,%1,%2,%3};"
                        : "+f"(d[mt][nc][0]), "+f"(d[mt][nc][1]),
                          "+f"(d[mt][nc][2]), "+f"(d[mt][nc][3])
                        : "r"(al[mt][0]), "r"(al[mt][1]), "r"(al[mt][2]), "r"(al[mt][3]),
                          "r"(b0), "r"(b1));
                }
            }
        }

        __syncthreads();                 // everyone done reading Xs/Ws

        const float pre   = (L == 0) ? pre0 : 1.0f;
        const bool addres = (L == 2) || (L == 4);
        const bool saver  = (L == 0) || (L == 2);

#pragma unroll
        for (int mt = 0; mt < 2; ++mt) {
#pragma unroll
            for (int nc = 0; nc < 4; ++nc) {
                float v[4];
#pragma unroll
                for (int j = 0; j < 4; ++j) {
                    float y = ssilu(pre * d[mt][nc][j]);
                    if (addres) y = (res[mt][nc][j] + y) * inv_sqrt2;
                    if (saver)  res[mt][nc][j] = y;
                    v[j] = y;
                }
                const int ra = m0 + 16 * mt + g;
                const int rb = ra + 8;
                const int c  = nb + 8 * nc + 2 * ti;
                if (L < 4) {
                    split_store_h(XsH, XsL, ra * SPAD + c, v[0], v[1]);
                    split_store_h(XsH, XsL, rb * SPAD + c, v[2], v[3]);
                } else {
                    if (row0 + ra < nRows)
                        *(float2*)&out[(size_t)(row0 + ra) * 128 + c] =
                            make_float2(v[0], v[1]);
                    if (row0 + rb < nRows)
                        *(float2*)&out[(size_t)(row0 + rb) * 128 + c] =
                            make_float2(v[2], v[3]);
                }
            }
        }

        if (L < 4) load_w_h(Wres + (size_t)L * 16384, Ws, tid);
    }
}

// ---------------------------------------------------------------------------
extern "C" void kernel_launch(void* const* d_in, const int* in_sizes, int n_in,
                              void* d_out, int out_size)
{
    // metadata order: nAtoms, m, rbf, id_j, W_rbf, scale, W1, W_res
    const float* m     = (const float*)d_in[1];
    const float* rbf   = (const float*)d_in[2];
    const int*   idj   = (const int*)  d_in[3];
    const float* Wrbf  = (const float*)d_in[4];
    const float* scale = (const float*)d_in[5];
    const float* W1    = (const float*)d_in[6];
    const float* Wres  = (const float*)d_in[7];

    int E      = in_sizes[1] / 128;
    int nAtoms = out_size / 128;
    if (nAtoms > CAP_ATOMS) nAtoms = CAP_ATOMS;
    if (E > CAP_EDGES) E = CAP_EDGES;

    float* px2 = nullptr;
    int *pcounts = nullptr, *poffs = nullptr, *pcursor = nullptr, *pbsums = nullptr;
    unsigned long long* ppk = nullptr;
    cudaGetSymbolAddress((void**)&px2, g_x2);
    cudaGetSymbolAddress((void**)&pcounts, g_counts);
    cudaGetSymbolAddress((void**)&poffs,   g_offs);
    cudaGetSymbolAddress((void**)&pcursor, g_cursor);
    cudaGetSymbolAddress((void**)&pbsums,  g_bsums);
    cudaGetSymbolAddress((void**)&ppk,     g_pk);

    cudaFuncSetAttribute(fused_mlp_kernel,
                         cudaFuncAttributeMaxDynamicSharedMemorySize, MLP_DSMEM);

    // CSR sort of edges by atom (packed eid|aid)
    zero_int_kernel<<<256, 256>>>(pcounts, CAP_ATOMS / 4);
    hist_kernel<<<2048, 256>>>(idj, pcounts, E);
    int nb = (nAtoms + 1023) / 1024;
    scan1_kernel<<<nb, 256>>>(pcounts, poffs, pbsums, nAtoms);
    scan2_kernel<<<1, 128>>>(pbsums, nb);
    scan3_kernel<<<(nAtoms + 255) / 256, 256>>>(pbsums, poffs, pcursor, nAtoms);
    fill_kernel<<<2048, 256>>>(idj, pcursor, ppk, E);

    // zero accumulator + per-edge pipelined scatter (CHUNK=128)
    int n4 = nAtoms * 128 / 4;
    zero_kernel<<<2048, 256>>>(px2, n4);
    int nchunks = (E + CHUNK - 1) / CHUNK;
    edge_pipe_kernel<<<(nchunks + 7) / 8, 256>>>(m, rbf, ppk, Wrbf, px2, E);

    // fused MLP (fp16 2-term)
    int grid = (nAtoms + 127) / 128;
    fused_mlp_kernel<<<grid, 512, MLP_DSMEM>>>(px2, W1, Wres, scale,
                                               (float*)d_out, nAtoms);
}

// round 17
// speedup vs baseline: 1.3326x; 1.0980x over previous
#include <cuda_runtime.h>
#include <cuda_fp16.h>
#include <cstdint>

// ---------------------------------------------------------------------------
// AtomUpdateBlock on GB300 (plain sm_103 feature set).
// Edge stage: CSR sort (packed eid|aid) + PERSISTENT per-edge 8-stage cp.async
//             pipelined run-accumulated scatter. 2368 resident warps grid-
//             stride over CHUNK=128 chunks: weight preload paid once per warp
//             (3.3x fewer than R16), tail imbalance smoothed.
// MLP stage: fused 5-layer HMMA kernel, fp16 2-term split (R15-proven).
// ---------------------------------------------------------------------------

#define CAP_ATOMS 131072
#define CAP_EDGES (1 << 21)

__device__ float              g_x2[CAP_ATOMS * 128];
__device__ int                g_counts[CAP_ATOMS];
__device__ int                g_offs  [CAP_ATOMS];
__device__ int                g_cursor[CAP_ATOMS];
__device__ int                g_bsums [256];
__device__ unsigned long long g_pk    [CAP_EDGES];   // lo32=eid, hi32=aid

__device__ __forceinline__ float ssilu(float x) {
    return x * (1.0f / (1.0f + __expf(-x))) * 1.6666666666666667f;
}

// ============================ zero / CSR build ==============================
__global__ void __launch_bounds__(256) zero_kernel(float* __restrict__ p, int n4) {
    int i = blockIdx.x * blockDim.x + threadIdx.x;
    int stride = gridDim.x * blockDim.x;
    float4 z = make_float4(0.f, 0.f, 0.f, 0.f);
    for (; i < n4; i += stride) ((float4*)p)[i] = z;
}

__global__ void __launch_bounds__(256) zero_int_kernel(int* __restrict__ p, int n4) {
    int i = blockIdx.x * blockDim.x + threadIdx.x;
    int stride = gridDim.x * blockDim.x;
    int4 z = make_int4(0, 0, 0, 0);
    for (; i < n4; i += stride) ((int4*)p)[i] = z;
}

__global__ void __launch_bounds__(256) hist_kernel(const int* __restrict__ idj,
                                                   int* __restrict__ counts, int E) {
    int i = blockIdx.x * blockDim.x + threadIdx.x;
    int stride = gridDim.x * blockDim.x;
    for (; i < E; i += stride) atomicAdd(&counts[__ldg(idj + i)], 1);
}

__global__ void __launch_bounds__(256) scan1_kernel(const int* __restrict__ counts,
                                                    int* __restrict__ offs,
                                                    int* __restrict__ bsums, int nAtoms) {
    __shared__ int sm[256];
    int t = threadIdx.x;
    int base = blockIdx.x * 1024 + t * 4;
    int c0 = 0, c1 = 0, c2 = 0, c3 = 0;
    if (base + 3 < nAtoms) {
        int4 c = *(const int4*)(counts + base);
        c0 = c.x; c1 = c.y; c2 = c.z; c3 = c.w;
    } else {
        if (base + 0 < nAtoms) c0 = counts[base + 0];
        if (base + 1 < nAtoms) c1 = counts[base + 1];
        if (base + 2 < nAtoms) c2 = counts[base + 2];
        if (base + 3 < nAtoms) c3 = counts[base + 3];
    }
    int T = c0 + c1 + c2 + c3;
    sm[t] = T;
    __syncthreads();
    for (int d = 1; d < 256; d <<= 1) {
        int v = (t >= d) ? sm[t - d] : 0;
        __syncthreads();
        sm[t] += v;
        __syncthreads();
    }
    int o = sm[t] - T;
    if (t == 255) bsums[blockIdx.x] = sm[255];
    if (base + 0 < nAtoms) offs[base + 0] = o; o += c0;
    if (base + 1 < nAtoms) offs[base + 1] = o; o += c1;
    if (base + 2 < nAtoms) offs[base + 2] = o; o += c2;
    if (base + 3 < nAtoms) offs[base + 3] = o;
}

__global__ void __launch_bounds__(128) scan2_kernel(int* __restrict__ bsums, int nb) {
    __shared__ int sm[128];
    int t = threadIdx.x;
    int v = (t < nb) ? bsums[t] : 0;
    sm[t] = v;
    __syncthreads();
    for (int d = 1; d < 128; d <<= 1) {
        int x = (t >= d) ? sm[t - d] : 0;
        __syncthreads();
        sm[t] += x;
        __syncthreads();
    }
    bsums[t] = sm[t] - v;
}

__global__ void __launch_bounds__(256) scan3_kernel(const int* __restrict__ bsums,
                                                    int* __restrict__ offs,
                                                    int* __restrict__ cursor,
                                                    int nAtoms) {
    int i = blockIdx.x * blockDim.x + threadIdx.x;
    if (i < nAtoms) {
        int v = offs[i] + __ldg(bsums + (i >> 10));
        offs[i] = v;
        cursor[i] = v;
    }
}

__global__ void __launch_bounds__(256) fill_kernel(const int* __restrict__ idj,
                                                   int* __restrict__ cursor,
                                                   unsigned long long* __restrict__ pk,
                                                   int E) {
    int i = blockIdx.x * blockDim.x + threadIdx.x;
    int stride = gridDim.x * blockDim.x;
    for (; i < E; i += stride) {
        int a = __ldg(idj + i);
        int p = atomicAdd(&cursor[a], 1);
        pk[p] = (unsigned long long)(unsigned)i
              | ((unsigned long long)(unsigned)a << 32);
    }
}

// ============================ persistent pipelined scatter ==================
#define CHUNK   128
#define STAGES  8
#define STG_B   576                                // 512B m row + 64B rbf
#define PK_B    (CHUNK * 8)                        // 1024B
#define WARP_SMEM (PK_B + STAGES * STG_B)          // 5632B
#define EDGE_BLOCKS 296                            // 148 SM x 2 CTA -> 2368 warps

__global__ void __launch_bounds__(256, 2) edge_pipe_kernel(
    const float* __restrict__ m,                 // [E,128]
    const float* __restrict__ rbf,               // [E,16]
    const unsigned long long* __restrict__ pk,   // [E] sorted: eid|aid<<32
    const float* __restrict__ Wr,                // [128,16]
    float*       __restrict__ out,               // [nAtoms,128] zeroed
    int E)
{
    __shared__ __align__(16) char smem[8 * WARP_SMEM];

    const int lane    = threadIdx.x & 31;
    const int wlocal  = threadIdx.x >> 5;
    const int gwarp   = (blockIdx.x * blockDim.x + threadIdx.x) >> 5;
    const int nwarps  = (gridDim.x * blockDim.x) >> 5;
    const int nchunks = (E + CHUNK - 1) / CHUNK;
    const int c0 = lane * 4;

    char* ws = smem + wlocal * WARP_SMEM;
    unsigned long long* s_pk = (unsigned long long*)ws;
    char* stages = ws + PK_B;
    uint32_t sbase;
    asm("{ .reg .u64 t; cvta.to.shared.u64 t, %1; cvt.u32.u64 %0, t; }"
        : "=r"(sbase) : "l"(stages));

    // ---- weights packed f32x2 in registers: ONCE per persistent warp
    unsigned long long wp0[16], wp1[16];
#pragma unroll
    for (int k = 0; k < 16; ++k) {
        float a = __ldg(&Wr[(c0 + 0) * 16 + k]);
        float b = __ldg(&Wr[(c0 + 1) * 16 + k]);
        float c = __ldg(&Wr[(c0 + 2) * 16 + k]);
        float d = __ldg(&Wr[(c0 + 3) * 16 + k]);
        asm("mov.b64 %0, {%1, %2};" : "=l"(wp0[k]) : "f"(a), "f"(b));
        asm("mov.b64 %0, {%1, %2};" : "=l"(wp1[k]) : "f"(c), "f"(d));
    }

    for (int chunk = gwarp; chunk < nchunks; chunk += nwarps) {
        const int base = chunk * CHUNK;
        const int n = (base + CHUNK <= E) ? CHUNK : (E - base);

        // ---- preload this chunk's pk entries to smem
        for (int j = lane; j < CHUNK; j += 32) {
            int gi = base + j;
            s_pk[j] = (gi < E) ? __ldg(pk + gi) : 0ull;
        }
        __syncwarp();

        // ---- pipeline prologue: issue STAGES edges
#pragma unroll
        for (int s = 0; s < STAGES; ++s) {
            if (s < n) {
                int e = (int)(unsigned)s_pk[s];
                uint32_t dm = sbase + s * STG_B + lane * 16;
                asm volatile("cp.async.ca.shared.global [%0], [%1], 16;"
                             :: "r"(dm), "l"(m + (size_t)e * 128 + lane * 4)
                             : "memory");
                if (lane < 4) {
                    uint32_t dr = sbase + s * STG_B + 512 + lane * 16;
                    asm volatile("cp.async.ca.shared.global [%0], [%1], 16;"
                                 :: "r"(dr), "l"(rbf + (size_t)e * 16 + lane * 4)
                                 : "memory");
                }
            }
            asm volatile("cp.async.commit_group;" ::: "memory");
        }

        int cur = (int)(s_pk[0] >> 32);
        float ax = 0.f, ay = 0.f, az = 0.f, aw = 0.f;

        for (int i = 0; i < n; ++i) {
            asm volatile("cp.async.wait_group 7;" ::: "memory");
            __syncwarp();

            const int s = i & (STAGES - 1);
            const int a = (int)(s_pk[i] >> 32);
            if (a != cur) {                          // warp-uniform
                float* dst = out + (size_t)cur * 128 + c0;
                asm volatile("red.global.add.v4.f32 [%0], {%1, %2, %3, %4};"
                             :: "l"(dst), "f"(ax), "f"(ay), "f"(az), "f"(aw)
                             : "memory");
                ax = ay = az = aw = 0.f;
                cur = a;
            }

            const float* st = (const float*)(stages + s * STG_B);
            float4 mv = *(const float4*)(st + lane * 4);
            float4 r0 = *(const float4*)(st + 128);
            float4 r1 = *(const float4*)(st + 132);
            float4 r2 = *(const float4*)(st + 136);
            float4 r3 = *(const float4*)(st + 140);

            float rk[16] = {r0.x, r0.y, r0.z, r0.w, r1.x, r1.y, r1.z, r1.w,
                            r2.x, r2.y, r2.z, r2.w, r3.x, r3.y, r3.z, r3.w};
            unsigned long long d01 = 0ull, d23 = 0ull;
#pragma unroll
            for (int k = 0; k < 16; ++k) {
                unsigned long long rp;
                asm("mov.b64 %0, {%1, %1};" : "=l"(rp) : "f"(rk[k]));
                asm("fma.rn.f32x2 %0, %1, %2, %0;" : "+l"(d01) : "l"(rp), "l"(wp0[k]));
                asm("fma.rn.f32x2 %0, %1, %2, %0;" : "+l"(d23) : "l"(rp), "l"(wp1[k]));
            }
            float v0, v1, v2, v3;
            asm("mov.b64 {%0, %1}, %2;" : "=f"(v0), "=f"(v1) : "l"(d01));
            asm("mov.b64 {%0, %1}, %2;" : "=f"(v2), "=f"(v3) : "l"(d23));
            ax = fmaf(v0, mv.x, ax);
            ay = fmaf(v1, mv.y, ay);
            az = fmaf(v2, mv.z, az);
            aw = fmaf(v3, mv.w, aw);

            // ---- refill slot s with edge i+STAGES
            __syncwarp();
            const int j = i + STAGES;
            if (j < n) {
                int e = (int)(unsigned)s_pk[j];
                uint32_t dm = sbase + s * STG_B + lane * 16;
                asm volatile("cp.async.ca.shared.global [%0], [%1], 16;"
                             :: "r"(dm), "l"(m + (size_t)e * 128 + lane * 4)
                             : "memory");
                if (lane < 4) {
                    uint32_t dr = sbase + s * STG_B + 512 + lane * 16;
                    asm volatile("cp.async.ca.shared.global [%0], [%1], 16;"
                                 :: "r"(dr), "l"(rbf + (size_t)e * 16 + lane * 4)
                                 : "memory");
                }
            }
            asm volatile("cp.async.commit_group;" ::: "memory");
        }

        float* dst = out + (size_t)cur * 128 + c0;
        asm volatile("red.global.add.v4.f32 [%0], {%1, %2, %3, %4};"
                     :: "l"(dst), "f"(ax), "f"(ay), "f"(az), "f"(aw) : "memory");
        // ≤7 pending groups here are all empty commits (refills guarded j<n),
        // so stage reuse next chunk is safe without a drain.
    }
}

// ============================ fused MLP (fp16 2-term, R15) ==================
#define SPAD 136
#define TILE (128 * SPAD)
#define MLP_DSMEM (3 * TILE * 2)           // XsH, XsL, Ws = 104448 B

__device__ __forceinline__ void split_store_h(
    __half* __restrict__ hi, __half* __restrict__ lo,
    int idx, float x, float y)
{
    __half hx = __float2half_rn(x);
    __half hy = __float2half_rn(y);
    __half lx = __float2half_rn(x - __half2float(hx));
    __half ly = __float2half_rn(y - __half2float(hy));
    __half2 hp = __halves2half2(hx, hy);
    __half2 lp = __halves2half2(lx, ly);
    *(uint32_t*)&hi[idx] = *(uint32_t*)&hp;
    *(uint32_t*)&lo[idx] = *(uint32_t*)&lp;
}

__device__ __forceinline__ void load_w_h(
    const float* __restrict__ W, __half* __restrict__ Ws, int tid)
{
    for (int i = tid; i < 128 * 32; i += 512) {
        int row = i >> 5, k4 = i & 31;
        int so = row * SPAD + 4 * k4;
        float4 w = __ldg((const float4*)(W + (size_t)row * 128) + k4);
        __half2 p0 = __halves2half2(__float2half_rn(w.x), __float2half_rn(w.y));
        __half2 p1 = __halves2half2(__float2half_rn(w.z), __float2half_rn(w.w));
        *(uint2*)&Ws[so] = make_uint2(*(uint32_t*)&p0, *(uint32_t*)&p1);
    }
}

__global__ void __launch_bounds__(512, 1) fused_mlp_kernel(
    const float* __restrict__ X,
    const float* __restrict__ W1,
    const float* __restrict__ Wres,
    const float* __restrict__ scale_ptr,
    float*       __restrict__ out,
    int nRows)
{
    extern __shared__ __align__(16) __half smem[];
    __half* XsH = smem;
    __half* XsL = smem + TILE;
    __half* Ws  = smem + 2 * TILE;

    const int tid  = threadIdx.x;
    const int row0 = blockIdx.x * 128;

    for (int i = tid; i < 128 * 32; i += 512) {
        int row = i >> 5, k4 = i & 31;
        int so = row * SPAD + 4 * k4;
        float4 v = make_float4(0.f, 0.f, 0.f, 0.f);
        if (row0 + row < nRows)
            v = __ldg((const float4*)(X + (size_t)(row0 + row) * 128) + k4);
        split_store_h(XsH, XsL, so,     v.x, v.y);
        split_store_h(XsH, XsL, so + 2, v.z, v.w);
    }
    load_w_h(W1, Ws, tid);

    const int wid  = tid >> 5;
    const int lane = tid & 31;
    const int g    = lane >> 2;
    const int ti   = lane & 3;
    const int m0   = (wid & 3) * 32;
    const int nb   = (wid >> 2) * 32;

    const float pre0 = scale_ptr ? __ldg(scale_ptr) : 1.0f;
    const float inv_sqrt2 = 0.70710678118654752440f;

    float res[2][4][4];

#pragma unroll 1
    for (int L = 0; L < 5; ++L) {
        __syncthreads();                 // Xs/Ws stores visible

        float d[2][4][4];
#pragma unroll
        for (int mt = 0; mt < 2; ++mt)
#pragma unroll
            for (int nc = 0; nc < 4; ++nc)
#pragma unroll
                for (int j = 0; j < 4; ++j) d[mt][nc][j] = 0.f;

#pragma unroll
        for (int ks = 0; ks < 8; ++ks) {
            const int k0 = ks * 16;
            uint32_t ah[2][4], al[2][4];
#pragma unroll
            for (int mt = 0; mt < 2; ++mt) {
                const int r = m0 + 16 * mt + g;
                ah[mt][0] = *(const uint32_t*)&XsH[(r)     * SPAD + k0 + 2 * ti];
                ah[mt][1] = *(const uint32_t*)&XsH[(r + 8) * SPAD + k0 + 2 * ti];
                ah[mt][2] = *(const uint32_t*)&XsH[(r)     * SPAD + k0 + 2 * ti + 8];
                ah[mt][3] = *(const uint32_t*)&XsH[(r + 8) * SPAD + k0 + 2 * ti + 8];
                al[mt][0] = *(const uint32_t*)&XsL[(r)     * SPAD + k0 + 2 * ti];
                al[mt][1] = *(const uint32_t*)&XsL[(r + 8) * SPAD + k0 + 2 * ti];
                al[mt][2] = *(const uint32_t*)&XsL[(r)     * SPAD + k0 + 2 * ti + 8];
                al[mt][3] = *(const uint32_t*)&XsL[(r + 8) * SPAD + k0 + 2 * ti + 8];
            }
#pragma unroll
            for (int nc = 0; nc < 4; ++nc) {
                const int n = nb + 8 * nc + g;
                uint32_t b0 = *(const uint32_t*)&Ws[n * SPAD + k0 + 2 * ti];
                uint32_t b1 = *(const uint32_t*)&Ws[n * SPAD + k0 + 2 * ti + 8];
#pragma unroll
                for (int mt = 0; mt < 2; ++mt) {
                    asm volatile(
                        "mma.sync.aligned.m16n8k16.row.col.f32.f16.f16.f32 "
                        "{%0,%1,%2,%3}, {%4,%5,%6,%7}, {%8,%9}, {%0,%1,%2,%3};"
                        : "+f"(d[mt][nc][0]), "+f"(d[mt][nc][1]),
                          "+f"(d[mt][nc][2]), "+f"(d[mt][nc][3])
                        : "r"(ah[mt][0]), "r"(ah[mt][1]), "r"(ah[mt][2]), "r"(ah[mt][3]),
                          "r"(b0), "r"(b1));
                    asm volatile(
                        "mma.sync.aligned.m16n8k16.row.col.f32.f16.f16.f32 "
                        "{%0,%1,%2,%3}, {%4,%5,%6,%7}, {%8,%9}, {%0,%1,%2,%3};"
                        : "+f"(d[mt][nc][0]), "+f"(d[mt][nc][1]),
                          "+f"(d[mt][nc][2]), "+f"(d[mt][nc][3])
                        : "r"(al[mt][0]), "r"(al[mt][1]), "r"(al[mt][2]), "r"(al[mt][3]),
                          "r"(b0), "r"(b1));
                }
            }
        }

        __syncthreads();                 // everyone done reading Xs/Ws

        const float pre   = (L == 0) ? pre0 : 1.0f;
        const bool addres = (L == 2) || (L == 4);
        const bool saver  = (L == 0) || (L == 2);

#pragma unroll
        for (int mt = 0; mt < 2; ++mt) {
#pragma unroll
            for (int nc = 0; nc < 4; ++nc) {
                float v[4];
#pragma unroll
                for (int j = 0; j < 4; ++j) {
                    float y = ssilu(pre * d[mt][nc][j]);
                    if (addres) y = (res[mt][nc][j] + y) * inv_sqrt2;
                    if (saver)  res[mt][nc][j] = y;
                    v[j] = y;
                }
                const int ra = m0 + 16 * mt + g;
                const int rb = ra + 8;
                const int c  = nb + 8 * nc + 2 * ti;
                if (L < 4) {
                    split_store_h(XsH, XsL, ra * SPAD + c, v[0], v[1]);
                    split_store_h(XsH, XsL, rb * SPAD + c, v[2], v[3]);
                } else {
                    if (row0 + ra < nRows)
                        *(float2*)&out[(size_t)(row0 + ra) * 128 + c] =
                            make_float2(v[0], v[1]);
                    if (row0 + rb < nRows)
                        *(float2*)&out[(size_t)(row0 + rb) * 128 + c] =
                            make_float2(v[2], v[3]);
                }
            }
        }

        if (L < 4) load_w_h(Wres + (size_t)L * 16384, Ws, tid);
    }
}

// ---------------------------------------------------------------------------
extern "C" void kernel_launch(void* const* d_in, const int* in_sizes, int n_in,
                              void* d_out, int out_size)
{
    // metadata order: nAtoms, m, rbf, id_j, W_rbf, scale, W1, W_res
    const float* m     = (const float*)d_in[1];
    const float* rbf   = (const float*)d_in[2];
    const int*   idj   = (const int*)  d_in[3];
    const float* Wrbf  = (const float*)d_in[4];
    const float* scale = (const float*)d_in[5];
    const float* W1    = (const float*)d_in[6];
    const float* Wres  = (const float*)d_in[7];

    int E      = in_sizes[1] / 128;
    int nAtoms = out_size / 128;
    if (nAtoms > CAP_ATOMS) nAtoms = CAP_ATOMS;
    if (E > CAP_EDGES) E = CAP_EDGES;

    float* px2 = nullptr;
    int *pcounts = nullptr, *poffs = nullptr, *pcursor = nullptr, *pbsums = nullptr;
    unsigned long long* ppk = nullptr;
    cudaGetSymbolAddress((void**)&px2, g_x2);
    cudaGetSymbolAddress((void**)&pcounts, g_counts);
    cudaGetSymbolAddress((void**)&poffs,   g_offs);
    cudaGetSymbolAddress((void**)&pcursor, g_cursor);
    cudaGetSymbolAddress((void**)&pbsums,  g_bsums);
    cudaGetSymbolAddress((void**)&ppk,     g_pk);

    cudaFuncSetAttribute(fused_mlp_kernel,
                         cudaFuncAttributeMaxDynamicSharedMemorySize, MLP_DSMEM);

    // CSR sort of edges by atom (packed eid|aid)
    zero_int_kernel<<<256, 256>>>(pcounts, CAP_ATOMS / 4);
    hist_kernel<<<2048, 256>>>(idj, pcounts, E);
    int nb = (nAtoms + 1023) / 1024;
    scan1_kernel<<<nb, 256>>>(pcounts, poffs, pbsums, nAtoms);
    scan2_kernel<<<1, 128>>>(pbsums, nb);
    scan3_kernel<<<(nAtoms + 255) / 256, 256>>>(pbsums, poffs, pcursor, nAtoms);
    fill_kernel<<<2048, 256>>>(idj, pcursor, ppk, E);

    // zero accumulator + persistent pipelined scatter
    int n4 = nAtoms * 128 / 4;
    zero_kernel<<<2048, 256>>>(px2, n4);
    int nchunks = (E + CHUNK - 1) / CHUNK;
    int eblocks = (nchunks + 7) / 8;
    if (eblocks > EDGE_BLOCKS) eblocks = EDGE_BLOCKS;
    edge_pipe_kernel<<<eblocks, 256>>>(m, rbf, ppk, Wrbf, px2, E);

    // fused MLP (fp16 2-term)
    int grid = (nAtoms + 127) / 128;
    fused_mlp_kernel<<<grid, 512, MLP_DSMEM>>>(px2, W1, Wres, scale,
                                               (float*)d_out, nAtoms);
}